// round 14
// baseline (speedup 1.0000x reference)
#include <cuda_runtime.h>
#include <cstdint>

#define B_SZ   64
#define IN_F   8192
#define OUT_F  8192
#define NNZ    262144
#define K8     8
#define CAP    96                   // padded slots per row; P(Poisson(32) > 96) ~ 1e-19
#define SPMM_BLOCKS 592             // 148 SMs * 4 resident blocks
#define TANH_BLOCKS 512
#define SCAT_BLOCKS 512             // 2 edges/thread

// ---------------- device scratch (no allocations allowed) ----------------
__device__ __align__(16) float  g_t[(size_t)IN_F * B_SZ];    // 2 MB, [col][batch]
__device__ int    g_cursor[OUT_F];    // zero-init; scatter fills, spmm resets to 0
__device__ int    g_ticket;           // spmm scheduler; reset by build block 0
__device__ int    g_c[(size_t)OUT_F * CAP];                  // cols, padded CSR (3MB)
__device__ __align__(16) float g_p[(size_t)OUT_F * CAP * K8]; // mono coeffs (25MB)

__device__ __forceinline__ void cheb2mono(float4 a, float4 b, float4& p0, float4& p1) {
    p0.x = a.x - a.z + b.x - b.z;
    p0.y = a.y - 3.f*a.w + 5.f*b.y - 7.f*b.w;
    p0.z = 2.f*a.z - 8.f*b.x + 18.f*b.z;
    p0.w = 4.f*a.w - 20.f*b.y + 56.f*b.w;
    p1.x = 8.f*b.x - 48.f*b.z;
    p1.y = 16.f*b.y - 112.f*b.w;
    p1.z = 32.f*b.z;
    p1.w = 64.f*b.w;
}

// ---------------- K1: FUSED build — tanh tiles + padded-CSR scatter --------
// blocks [0,512): 32x32 tanh transpose tiles.  blocks [512,1024): scatter,
// 2 edges/thread. The two halves are independent and co-schedule on the chip.
__global__ void __launch_bounds__(256) build_kernel(const float* __restrict__ x,
                                                    const int*   __restrict__ rows,
                                                    const int*   __restrict__ cols,
                                                    const float* __restrict__ weight) {
    __shared__ float tile[32][33];
    int tid = threadIdx.x;
    int bx  = blockIdx.x;

    if (bx < TANH_BLOCKS) {
        if (bx == 0 && tid == 0) g_ticket = 0;     // reset spmm scheduler
        int tx = tid & 31, ty = tid >> 5;
        int c0 = (bx & 255) * 32, b0 = (bx >> 8) * 32;
        const float CLIP = 1.0f - 1e-7f;
#pragma unroll
        for (int i = 0; i < 4; i++) {
            int b = b0 + ty + i * 8;
            float xv = x[(size_t)b * IN_F + c0 + tx];
            float e  = __expf(2.0f * xv);          // tanh = 1 - 2/(e^{2x}+1)
            float t  = 1.0f - 2.0f / (e + 1.0f);
            tile[ty + i * 8][tx] = fminf(fmaxf(t, -CLIP), CLIP);
        }
        __syncthreads();
#pragma unroll
        for (int i = 0; i < 4; i++) {
            int c = c0 + ty + i * 8;
            g_t[(size_t)c * B_SZ + b0 + tx] = tile[tx][ty + i * 8];
        }
    } else {
        int e0 = ((bx - TANH_BLOCKS) * 256 + tid) * 2;
        int2 r2 = *reinterpret_cast<const int2*>(rows + e0);
        int2 c2 = *reinterpret_cast<const int2*>(cols + e0);
        // two independent atomics in flight
        int p0 = atomicAdd(&g_cursor[r2.x], 1);
        int p1 = atomicAdd(&g_cursor[r2.y], 1);
        const float4* wp = reinterpret_cast<const float4*>(weight + (size_t)e0 * K8);
        int   pos[2] = {p0, p1};
        int   rr[2]  = {r2.x, r2.y};
        int   cc[2]  = {c2.x, c2.y};
#pragma unroll
        for (int k = 0; k < 2; k++) {
            if (pos[k] < CAP) {                    // overflow guard (never expected)
                size_t slot = (size_t)rr[k] * CAP + pos[k];
                float4 a = wp[2 * k], b = wp[2 * k + 1];
                float4 q0, q1;
                cheb2mono(a, b, q0, q1);
                g_c[slot] = cc[k];
                float4* dst = reinterpret_cast<float4*>(g_p + slot * K8);
                dst[0] = q0;
                dst[1] = q1;
            }
        }
    }
}

// ---------------- K2: main SpMM — R11 hot loop, padded CSR -----------------
// One warp per row (dynamic ticket). Lane owns batches (2l, 2l+1).
// c 2 chunks ahead; t 1 chunk ahead (float2/lane); w-lines L1-warmed,
// consumed per-edge via uniform broadcast LDG.128.
__global__ void __launch_bounds__(256, 4) spmm_kernel(float* __restrict__ out) {
    int lane  = threadIdx.x & 31;
    int lane2 = lane * 2;

    for (;;) {
        int r;
        if (lane == 0) r = atomicAdd(&g_ticket, 1);
        r = __shfl_sync(0xFFFFFFFFu, r, 0);
        if (r >= OUT_F) return;

        int n = g_cursor[r];                   // uniform load (broadcast)
        n = min(n, CAP);
        if (lane == 0) g_cursor[r] = 0;        // reset for next call

        const int*   cp = g_c + (size_t)r * CAP;
        const float* pp = g_p + (size_t)r * CAP * K8;

        float acc0 = 0.0f, acc1 = 0.0f;

        if (n > 0) {
            float2 tA[8], tB[8];
            float  wA, wB;                     // L1-warming regs (kept alive via asm)
            int    cA, cB, cN;
            size_t wmax = (size_t)n * K8 - 1;

#define LC(base_) __ldg(cp + min((base_) + (lane & 7), n - 1))

#define LTW(tb, wv, creg, base_)                                                 \
    do {                                                                         \
        _Pragma("unroll")                                                        \
        for (int _i = 0; _i < 8; _i++) {                                         \
            int _cc = __shfl_sync(0xFFFFFFFFu, (creg), _i);                      \
            (tb)[_i] = *reinterpret_cast<const float2*>(                         \
                g_t + ((size_t)_cc << 6) + lane2);                               \
        }                                                                        \
        size_t _w0 = (size_t)(base_) * K8 + lane2;                               \
        (wv) = __ldg(pp + (_w0 <= wmax ? _w0 : wmax));                           \
        asm volatile("" :: "f"(wv));   /* keep warming load alive */             \
    } while (0)

#define EDGE(tv, gi)                                                             \
    do {                                                                         \
        if ((gi) < n) {                                                          \
            const float4* _u = reinterpret_cast<const float4*>(                  \
                pp + (size_t)(gi) * K8);                                         \
            float4 u0 = __ldg(_u);                                               \
            float4 u1 = __ldg(_u + 1);                                           \
            float tx = (tv).x, ty = (tv).y;                                      \
            float h0 = u1.w, h1 = u1.w;                                          \
            h0 = fmaf(h0, tx, u1.z); h1 = fmaf(h1, ty, u1.z);                    \
            h0 = fmaf(h0, tx, u1.y); h1 = fmaf(h1, ty, u1.y);                    \
            h0 = fmaf(h0, tx, u1.x); h1 = fmaf(h1, ty, u1.x);                    \
            h0 = fmaf(h0, tx, u0.w); h1 = fmaf(h1, ty, u0.w);                    \
            h0 = fmaf(h0, tx, u0.z); h1 = fmaf(h1, ty, u0.z);                    \
            h0 = fmaf(h0, tx, u0.y); h1 = fmaf(h1, ty, u0.y);                    \
            h0 = fmaf(h0, tx, u0.x); h1 = fmaf(h1, ty, u0.x);                    \
            acc0 += h0; acc1 += h1;                                              \
        }                                                                        \
    } while (0)

#define COMPUTE(tb, base_)                                                       \
    do {                                                                         \
        EDGE((tb)[0], (base_) + 0);                                              \
        EDGE((tb)[1], (base_) + 1);                                              \
        EDGE((tb)[2], (base_) + 2);                                              \
        EDGE((tb)[3], (base_) + 3);                                              \
        EDGE((tb)[4], (base_) + 4);                                              \
        EDGE((tb)[5], (base_) + 5);                                              \
        EDGE((tb)[6], (base_) + 6);                                              \
        EDGE((tb)[7], (base_) + 7);                                              \
    } while (0)

            cA = LC(0);
            cB = LC(8);
            LTW(tA, wA, cA, 0);
            for (int base = 0; base < n; base += 16) {
                cN = LC(base + 16);
                LTW(tB, wB, cB, base + 8);
                COMPUTE(tA, base);
                cB = LC(base + 24);
                LTW(tA, wA, cN, base + 16);
                COMPUTE(tB, base + 8);
            }
#undef LC
#undef LTW
#undef EDGE
#undef COMPUTE
        }

        out[(size_t)lane2 * OUT_F + r]       = acc0;
        out[(size_t)(lane2 + 1) * OUT_F + r] = acc1;
    }
}

// ---------------- launcher ----------------
extern "C" void kernel_launch(void* const* d_in, const int* in_sizes, int n_in,
                              void* d_out, int out_size) {
    const float* x      = (const float*)d_in[0];   // [64, 8192]
    const float* weight = (const float*)d_in[1];   // [262144, 8]
    const int*   rows   = (const int*)  d_in[2];   // [262144]
    const int*   cols   = (const int*)  d_in[3];   // [262144]
    float*       out    = (float*)d_out;           // [64, 8192]

    build_kernel<<<TANH_BLOCKS + SCAT_BLOCKS, 256>>>(x, rows, cols, weight);
    spmm_kernel <<<SPMM_BLOCKS, 256>>>(out);
}

// round 15
// speedup vs baseline: 1.4988x; 1.4988x over previous
#include <cuda_runtime.h>
#include <cstdint>

#define B_SZ   64
#define IN_F   8192
#define OUT_F  8192
#define NNZ    262144
#define K8     8
#define SPMM_BLOCKS 592             // 148 SMs * 4 resident blocks

// ---------------- device scratch (no allocations allowed) ----------------
__device__ __align__(16) float  g_t[(size_t)IN_F * B_SZ];   // 2 MB, [col][batch]
__device__ int    g_count[OUT_F];     // zero-init at load; re-zeroed by spmm each call
__device__ int    g_start[OUT_F];
__device__ int    g_cursor[OUT_F];    // after scatter: start + n
__device__ int    g_order[OUT_F];     // rows sorted by descending edge count (LPT)
__device__ int    g_ticket;           // spmm scheduler; reset by scan
__device__ int    g_c[NNZ];                                  // cols in CSR order (dense)
__device__ __align__(16) float g_p[(size_t)NNZ * K8];        // monomial coeffs, CSR (8MB)

// ---------------- K1: tanh table (smem tile transpose) + row histogram -----
__global__ void tanh_hist_kernel(const float* __restrict__ x,
                                 const int*   __restrict__ rows) {
    __shared__ float tile[32][33];
    int tx = threadIdx.x, ty = threadIdx.y;
    int flat = (blockIdx.y * gridDim.x + blockIdx.x) * 256 + ty * 32 + tx;
    int e0 = flat * 2;                 // 512*256*2 == NNZ
    atomicAdd(&g_count[rows[e0]], 1);
    atomicAdd(&g_count[rows[e0 + 1]], 1);

    int c0 = blockIdx.x * 32, b0 = blockIdx.y * 32;
    const float CLIP = 1.0f - 1e-7f;
#pragma unroll
    for (int i = 0; i < 4; i++) {
        int b = b0 + ty + i * 8;
        float xv = x[(size_t)b * IN_F + c0 + tx];
        float e  = __expf(2.0f * xv);          // tanh = 1 - 2/(e^{2x}+1)
        float t  = 1.0f - 2.0f / (e + 1.0f);
        tile[ty + i * 8][tx] = fminf(fmaxf(t, -CLIP), CLIP);
    }
    __syncthreads();
#pragma unroll
    for (int i = 0; i < 4; i++) {
        int c = c0 + ty + i * 8;
        g_t[(size_t)c * B_SZ + b0 + tx] = tile[tx][ty + i * 8]; // coalesced over b
    }
}

// ------ K2: exclusive scan over 8192 counters + LPT counting sort (1 CTA) --
__global__ void scan_kernel() {
    __shared__ int wsum[32];
    __shared__ int bin_base[128];      // cursor per length-bin (descending order)
    int t    = threadIdx.x;            // 0..1023
    int lane = t & 31, wid = t >> 5;
    if (t == 0) g_ticket = 0;          // reset spmm scheduler
    if (t < 128) bin_base[t] = 0;
    __syncthreads();

    int base = t * 8;
    int v[8], cnt[8];
    int run = 0;
#pragma unroll
    for (int i = 0; i < 8; i++) {
        cnt[i] = g_count[base + i];
        v[i] = run;
        run += cnt[i];
        atomicAdd(&bin_base[127 - min(cnt[i], 127)], 1);  // idx 0 = longest rows
    }
    // warp+block scan of per-thread totals (CSR offsets)
    int x = run;
#pragma unroll
    for (int off = 1; off < 32; off <<= 1) {
        int y = __shfl_up_sync(0xFFFFFFFFu, x, off);
        if (lane >= off) x += y;
    }
    if (lane == 31) wsum[wid] = x;
    __syncthreads();
    if (wid == 0) {
        int y = wsum[lane];
#pragma unroll
        for (int off = 1; off < 32; off <<= 1) {
            int z = __shfl_up_sync(0xFFFFFFFFu, y, off);
            if (lane >= off) y += z;
        }
        wsum[lane] = y;
    }
    __syncthreads();
    int warp_excl = (wid > 0) ? wsum[wid - 1] : 0;
    int thr_excl  = warp_excl + (x - run);
#pragma unroll
    for (int i = 0; i < 8; i++) {
        int st = thr_excl + v[i];
        g_start[base + i]  = st;
        g_cursor[base + i] = st;
    }

    // exclusive scan of the 128 bins (idx ascending = length descending)
    __syncthreads();
    if (wid < 4) {
        int bc = bin_base[t];
        int ix = bc;
#pragma unroll
        for (int off = 1; off < 32; off <<= 1) {
            int y = __shfl_up_sync(0xFFFFFFFFu, ix, off);
            if (lane >= off) ix += y;
        }
        if (lane == 31) wsum[wid] = ix;
        bin_base[t] = ix - bc;                  // intra-warp exclusive
    }
    __syncthreads();
    if (wid < 4) {
        int add = 0;
#pragma unroll
        for (int wI = 0; wI < 3; wI++) if (wI < wid) add += wsum[wI];
        bin_base[t] += add;                     // global exclusive base
    }
    __syncthreads();

    // scatter row ids into g_order by bin (LPT order)
#pragma unroll
    for (int i = 0; i < 8; i++) {
        int ix  = 127 - min(cnt[i], 127);
        int pos = atomicAdd(&bin_base[ix], 1);
        g_order[pos] = base + i;
    }
}

// -------- K3: scatter cols + Chebyshev->monomial coeffs, 1 edge/thread -----
// 262144 threads (1024 blocks): latency hidden by warp count, not per-thread MLP.
__device__ __forceinline__ void cheb2mono(float4 a, float4 b, float4& p0, float4& p1) {
    p0.x = a.x - a.z + b.x - b.z;
    p0.y = a.y - 3.f*a.w + 5.f*b.y - 7.f*b.w;
    p0.z = 2.f*a.z - 8.f*b.x + 18.f*b.z;
    p0.w = 4.f*a.w - 20.f*b.y + 56.f*b.w;
    p1.x = 8.f*b.x - 48.f*b.z;
    p1.y = 16.f*b.y - 112.f*b.w;
    p1.z = 32.f*b.z;
    p1.w = 64.f*b.w;
}

__global__ void scatter_kernel(const int*   __restrict__ rows,
                               const int*   __restrict__ cols,
                               const float* __restrict__ weight) {
    int i = blockIdx.x * blockDim.x + threadIdx.x;   // one edge per thread
    int r = rows[i];
    int c = cols[i];
    const float4* wp = reinterpret_cast<const float4*>(weight + (size_t)i * K8);
    float4 a = wp[0], b = wp[1];
    float4 q0, q1;
    cheb2mono(a, b, q0, q1);
    int p = atomicAdd(&g_cursor[r], 1);
    g_c[p] = c;
    float4* dst = reinterpret_cast<float4*>(g_p + (size_t)p * K8);
    dst[0] = q0;
    dst[1] = q1;
}

// ---------------- K4: main SpMM — LPT order, R11 hot loop ------------------
// One warp per row, longest rows first via g_order. Lane owns batches
// (2l, 2l+1). c 2 chunks ahead; t 1 chunk ahead; w-lines L1-warmed,
// consumed per-edge via uniform broadcast LDG.128.
__global__ void __launch_bounds__(256, 4) spmm_kernel(float* __restrict__ out) {
    int lane  = threadIdx.x & 31;
    int lane2 = lane * 2;

    for (;;) {
        int u;
        if (lane == 0) u = atomicAdd(&g_ticket, 1);
        u = __shfl_sync(0xFFFFFFFFu, u, 0);
        if (u >= OUT_F) return;
        int r = g_order[u];                   // LPT: longest rows first

        int start = g_start[r];
        int n     = g_cursor[r] - start;      // cursor holds start+n after scatter

        if (lane == 0) g_count[r] = 0;        // reset histogram for next call

        const int*   cp = g_c + start;
        const float* pp = g_p + (size_t)start * K8;

        float acc0 = 0.0f, acc1 = 0.0f;

        if (n > 0) {
            float2 tA[8], tB[8];
            float  wA, wB;                    // L1-warming regs (kept alive via asm)
            int    cA, cB, cN;
            size_t wmax = (size_t)n * K8 - 1;

#define LC(base_) __ldg(cp + min((base_) + (lane & 7), n - 1))

#define LTW(tb, wv, creg, base_)                                                 \
    do {                                                                         \
        _Pragma("unroll")                                                        \
        for (int _i = 0; _i < 8; _i++) {                                         \
            int _cc = __shfl_sync(0xFFFFFFFFu, (creg), _i);                      \
            (tb)[_i] = *reinterpret_cast<const float2*>(                         \
                g_t + ((size_t)_cc << 6) + lane2);                               \
        }                                                                        \
        size_t _w0 = (size_t)(base_) * K8 + lane2;                               \
        (wv) = __ldg(pp + (_w0 <= wmax ? _w0 : wmax));                           \
        asm volatile("" :: "f"(wv));   /* keep warming load alive */             \
    } while (0)

#define EDGE(tv, gi)                                                             \
    do {                                                                         \
        if ((gi) < n) {                                                          \
            const float4* _u = reinterpret_cast<const float4*>(                  \
                pp + (size_t)(gi) * K8);                                         \
            float4 u0 = __ldg(_u);                                               \
            float4 u1 = __ldg(_u + 1);                                           \
            float tx = (tv).x, ty = (tv).y;                                      \
            float h0 = u1.w, h1 = u1.w;                                          \
            h0 = fmaf(h0, tx, u1.z); h1 = fmaf(h1, ty, u1.z);                    \
            h0 = fmaf(h0, tx, u1.y); h1 = fmaf(h1, ty, u1.y);                    \
            h0 = fmaf(h0, tx, u1.x); h1 = fmaf(h1, ty, u1.x);                    \
            h0 = fmaf(h0, tx, u0.w); h1 = fmaf(h1, ty, u0.w);                    \
            h0 = fmaf(h0, tx, u0.z); h1 = fmaf(h1, ty, u0.z);                    \
            h0 = fmaf(h0, tx, u0.y); h1 = fmaf(h1, ty, u0.y);                    \
            h0 = fmaf(h0, tx, u0.x); h1 = fmaf(h1, ty, u0.x);                    \
            acc0 += h0; acc1 += h1;                                              \
        }                                                                        \
    } while (0)

#define COMPUTE(tb, base_)                                                       \
    do {                                                                         \
        EDGE((tb)[0], (base_) + 0);                                              \
        EDGE((tb)[1], (base_) + 1);                                              \
        EDGE((tb)[2], (base_) + 2);                                              \
        EDGE((tb)[3], (base_) + 3);                                              \
        EDGE((tb)[4], (base_) + 4);                                              \
        EDGE((tb)[5], (base_) + 5);                                              \
        EDGE((tb)[6], (base_) + 6);                                              \
        EDGE((tb)[7], (base_) + 7);                                              \
    } while (0)

            cA = LC(0);
            cB = LC(8);
            LTW(tA, wA, cA, 0);
            for (int base = 0; base < n; base += 16) {
                cN = LC(base + 16);
                LTW(tB, wB, cB, base + 8);
                COMPUTE(tA, base);
                cB = LC(base + 24);
                LTW(tA, wA, cN, base + 16);
                COMPUTE(tB, base + 8);
            }
#undef LC
#undef LTW
#undef EDGE
#undef COMPUTE
        }

        out[(size_t)lane2 * OUT_F + r]       = acc0;
        out[(size_t)(lane2 + 1) * OUT_F + r] = acc1;
    }
}

// ---------------- launcher ----------------
extern "C" void kernel_launch(void* const* d_in, const int* in_sizes, int n_in,
                              void* d_out, int out_size) {
    const float* x      = (const float*)d_in[0];   // [64, 8192]
    const float* weight = (const float*)d_in[1];   // [262144, 8]
    const int*   rows   = (const int*)  d_in[2];   // [262144]
    const int*   cols   = (const int*)  d_in[3];   // [262144]
    float*       out    = (float*)d_out;           // [64, 8192]

    dim3 tgrid(IN_F / 32, B_SZ / 32);              // 512 blocks
    dim3 tblk(32, 8);
    tanh_hist_kernel<<<tgrid, tblk>>>(x, rows);
    scan_kernel     <<<1, 1024>>>();
    scatter_kernel  <<<NNZ / 256, 256>>>(rows, cols, weight);
    spmm_kernel     <<<SPMM_BLOCKS, 256>>>(out);
}